// round 16
// baseline (speedup 1.0000x reference)
#include <cuda_runtime.h>
#include <cuda_bf16.h>
#include <math.h>
#include <stdint.h>

// ---------------- problem constants ----------------
#define DD 16
#define HH 256
#define MM 3
#define NN 65536

// ---------------- table config ----------------
#define T_TAB 142
#define NPTS  144              // 142 grid + x=-1 + x=+1; 9 M-tiles of 16
#define MTILE 16
#define BPN   9                // blocks per net -> 144 CTAs, one wave (<=148 SMs)
#define NCTA  (DD * BPN)       // 144: co-residency guaranteed at 1 CTA/SM
#define XMN   (-6.0f)
#define DXI   (12.0f / 141.0f)
#define INV_DX (141.0f / 12.0f)

// A smem pitch (bf16 elems): multiple of 8 (16B rows for ldmatrix),
// 560B rows -> ldmatrix row phases conflict-free.
#define APITCH 280
#define ABUFB  (MTILE * APITCH * 2)    // bytes per A buffer (8960)

// conversion smem pitch (fp32): gather banks (8tq + 8nt + g) mod 32 conflict-free
#define CPITCH 260

// ---------------- device scratch ----------------
__device__ float g_table[DD][T_TAB];
__device__ float g_ymm[DD][2];
// staged weights in mma-fragment order:
// index (((l*DD+d)*16 + ktile)*32 + ntile)*32 + lane -> {b0h, b1h, b0l, b1l}
__device__ __align__(16) uint4 g_B[MM * DD * 16 * 32 * 32];
#define LSTRIDE (DD * 16 * 32 * 32)    // uint4 elems between layers (262144)

// replay-safe epoch barrier counter (never reset; each launch adds exactly NCTA)
__device__ unsigned g_bar;

// ==================== helpers ====================
__device__ __forceinline__ uint32_t smem_to_u32(const void* smem_ptr) {
    uint32_t addr;
    asm("{ .reg .u64 tmp; cvta.to.shared.u64 tmp, %1; cvt.u32.u64 %0, tmp; }"
        : "=r"(addr) : "l"(smem_ptr));
    return addr;
}

// exact tanh identity via fast MUFU ex2/rcp: ~1e-7 abs err, saturates correctly
__device__ __forceinline__ float tanh_fast(float x) {
    float e = __expf(2.0f * x);
    return 1.0f - __fdividef(2.0f, e + 1.0f);
}

// (a,b) fp32 -> packed bf16x2 hi + bf16x2 lo (residual); lo16 = a, hi16 = b
__device__ __forceinline__ void split2(float a, float b, unsigned& hi, unsigned& lo) {
    __nv_bfloat16 ha = __float2bfloat16(a), hb = __float2bfloat16(b);
    __nv_bfloat16 la = __float2bfloat16(a - __bfloat162float(ha));
    __nv_bfloat16 lb = __float2bfloat16(b - __bfloat162float(hb));
    hi = (unsigned)__bfloat16_as_ushort(ha) | ((unsigned)__bfloat16_as_ushort(hb) << 16);
    lo = (unsigned)__bfloat16_as_ushort(la) | ((unsigned)__bfloat16_as_ushort(lb) << 16);
}

#define MMA_BF16(d, a, b0, b1) \
    asm volatile("mma.sync.aligned.m16n8k16.row.col.f32.bf16.bf16.f32 " \
        "{%0,%1,%2,%3}, {%4,%5,%6,%7}, {%8,%9}, {%0,%1,%2,%3};" \
        : "+f"((d)[0]), "+f"((d)[1]), "+f"((d)[2]), "+f"((d)[3]) \
        : "r"((a)[0]), "r"((a)[1]), "r"((a)[2]), "r"((a)[3]), "r"(b0), "r"(b1))

#define LDMATRIX_X4(r, addr) \
    asm volatile("ldmatrix.sync.aligned.m8n8.x4.shared.b16 {%0,%1,%2,%3}, [%4];" \
        : "=r"((r)[0]), "=r"((r)[1]), "=r"((r)[2]), "=r"((r)[3]) : "r"(addr))

// ---------------------------------------------------------------------------
// Fused build: 144 CTAs x 512 threads.
//  Phase A: cooperatively convert all 768 (nd, ktile) weight tiles -> g_B
//           (smem transpose buffer overlaid on the not-yet-used A_hi region).
//  Then:    per-CTA input layer (overlaps other CTAs' conversion tail).
//  Barrier: replay-safe epoch barrier (monotonic counter, +144 per launch).
//  Phase B: 3-layer HMMA build (identical to the 27.0us R15 build loop).
// ---------------------------------------------------------------------------
__global__ __launch_bounds__(512) void build_kernel(
    const float* __restrict__ W_in,  const float* __restrict__ b_in,
    const float* __restrict__ W_mid, const float* __restrict__ b_mid,
    const float* __restrict__ W_out, const float* __restrict__ b_out)
{
    __shared__ __align__(16) unsigned short A_hi[2][MTILE][APITCH];
    __shared__ __align__(16) unsigned short A_lo[2][MTILE][APITCH];
    __shared__ float red[16][MTILE];

    const int t    = threadIdx.x;
    const int wid  = t >> 5;
    const int lane = t & 31;
    const int tq   = lane & 3;
    const int g    = lane >> 2;
    const int cta  = blockIdx.x;
    const int d    = cta / BPN;
    const int blk  = cta % BPN;

    // ---- Phase A: weight conversion. s overlays A_hi (16*260*4=16640B <= 17920B)
    {
        float (*s)[CPITCH] = reinterpret_cast<float(*)[CPITCH]>(&A_hi[0][0][0]);
        for (int task = cta; task < MM * DD * 16; task += NCTA) {
            const int nd = task >> 4;
            const int kt = task & 15;
            const float* src = W_mid + ((size_t)nd << 16) + (size_t)(kt * 16) * 256;
            // load 16x256 fp32 tile: 1024 float4, 2 per thread, coalesced
            #pragma unroll
            for (int u = 0; u < 2; ++u) {
                const int idx = t + u * 512;
                const int r   = idx >> 6;
                const int c4  = (idx & 63) << 2;
                const float4 v = __ldg((const float4*)(src + r * 256 + c4));
                *(float4*)&s[r][c4] = v;
            }
            __syncthreads();
            // gather + split into fragment order: 1024 uint4, 2 per thread
            uint4* out = g_B + ((size_t)task << 10);
            #pragma unroll
            for (int u = 0; u < 2; ++u) {
                const int w    = t + u * 512;
                const int ln2  = w & 31;
                const int nt   = w >> 5;
                const int tq2  = ln2 & 3;
                const int g2   = ln2 >> 2;
                const int n    = nt * 8 + g2;
                const int k0   = 2 * tq2;
                unsigned b0h, b0l, b1h, b1l;
                split2(s[k0][n],     s[k0 + 1][n], b0h, b0l);
                split2(s[k0 + 8][n], s[k0 + 9][n], b1h, b1l);
                out[(nt << 5) + ln2] = make_uint4(b0h, b1h, b0l, b1l);
            }
            __syncthreads();
        }
    }

    // ---- input layer: A0[m][k] = tanh(W_in[k]*x_m + b_in[k]) -> buffer 0 ----
    {
        const int m  = t & 15;
        const int kc = t >> 4;        // k chunk of 8
        const int pidx = blk * MTILE + m;
        float xp;
        if (pidx < T_TAB)       xp = XMN + (float)pidx * DXI;
        else if (pidx == T_TAB) xp = -1.0f;
        else                    xp =  1.0f;
        const float* wi = W_in + d * HH;
        const float* bi = b_in + d * HH;
        #pragma unroll
        for (int kk = 0; kk < 8; kk += 2) {
            const int k = kc * 8 + kk;
            const float v0 = tanh_fast(fmaf(__ldg(&wi[k]),     xp, __ldg(&bi[k])));
            const float v1 = tanh_fast(fmaf(__ldg(&wi[k + 1]), xp, __ldg(&bi[k + 1])));
            unsigned hi, lo;
            split2(v0, v1, hi, lo);
            *(unsigned*)&A_hi[0][m][k] = hi;
            *(unsigned*)&A_lo[0][m][k] = lo;
        }
    }
    __syncthreads();

    // ---- grid barrier: all conversion writes visible before any g_B read ----
    if (t == 0) {
        __threadfence();
        const unsigned arrive = atomicAdd(&g_bar, 1u) + 1u;
        const unsigned target = ((arrive + (NCTA - 1u)) / NCTA) * NCTA;
        volatile unsigned* p = &g_bar;
        while (*p < target) { }
        __threadfence();
    }
    __syncthreads();

    // layer-0 B fragment load (post-barrier; latency exposed once)
    const uint4* __restrict__ Bw0 =
        g_B + ((size_t)d * 16 * 32 + wid * 2) * 32 + lane;
    uint4 Bc[2];
    Bc[0] = Bw0[0];
    Bc[1] = Bw0[32];

    const uint32_t Ahi_base = smem_to_u32(&A_hi[0][0][0]);
    const uint32_t Alo_base = smem_to_u32(&A_lo[0][0][0]);
    const uint32_t lm_off = (uint32_t)((lane & 15) * (APITCH * 2) + (lane >> 4) * 16);

    for (int l = 0; l < MM; ++l) {
        const int rb = l & 1;
        const int wb = rb ^ 1;
        const uint4* __restrict__ Bw =
            g_B + ((size_t)(l * DD + d) * 16 * 32 + wid * 2) * 32 + lane;
        const uint32_t rboff = (uint32_t)(rb * ABUFB);

        float acc[2][4];
        #pragma unroll
        for (int nt = 0; nt < 2; ++nt)
            #pragma unroll
            for (int e = 0; e < 4; ++e) acc[nt][e] = 0.0f;

        #pragma unroll 4
        for (int kt = 0; kt < 16; ++kt) {
            unsigned ah[4], al[4];
            const uint32_t ka = (uint32_t)(kt * 32);
            LDMATRIX_X4(ah, Ahi_base + rboff + lm_off + ka);
            LDMATRIX_X4(al, Alo_base + rboff + lm_off + ka);

            // prefetch: next k-tile, or next layer's first fragments
            uint4 Bn[2];
            if (kt < 15) {
                #pragma unroll
                for (int nt = 0; nt < 2; ++nt) Bn[nt] = Bw[(kt + 1) * 1024 + nt * 32];
            } else if (l < MM - 1) {
                #pragma unroll
                for (int nt = 0; nt < 2; ++nt) Bn[nt] = Bw[LSTRIDE + nt * 32];
            } else {
                #pragma unroll
                for (int nt = 0; nt < 2; ++nt) Bn[nt] = Bc[nt];
            }

            #pragma unroll
            for (int nt = 0; nt < 2; ++nt) {
                const unsigned b0h = Bc[nt].x, b1h = Bc[nt].y;
                const unsigned b0l = Bc[nt].z, b1l = Bc[nt].w;
                MMA_BF16(acc[nt], ah, b0h, b1h);   // Ahi * Bhi
                MMA_BF16(acc[nt], al, b0h, b1h);   // Alo * Bhi
                MMA_BF16(acc[nt], ah, b0l, b1l);   // Ahi * Blo
            }
            #pragma unroll
            for (int nt = 0; nt < 2; ++nt) Bc[nt] = Bn[nt];
        }

        if (l < MM - 1) {
            // epilogue -> write buffer wb (readers of rb are unaffected)
            const float* bm = b_mid + (size_t)(l * DD + d) * HH + wid * 16;
            #pragma unroll
            for (int nt = 0; nt < 2; ++nt) {
                const int ne = nt * 8 + tq * 2;
                const float2 bb = *(const float2*)&bm[ne];
                const int ncol = wid * 16 + ne;
                unsigned hi, lo;
                split2(tanh_fast(acc[nt][0] + bb.x),
                       tanh_fast(acc[nt][1] + bb.y), hi, lo);
                *(unsigned*)&A_hi[wb][g][ncol] = hi;
                *(unsigned*)&A_lo[wb][g][ncol] = lo;
                split2(tanh_fast(acc[nt][2] + bb.x),
                       tanh_fast(acc[nt][3] + bb.y), hi, lo);
                *(unsigned*)&A_hi[wb][g + 8][ncol] = hi;
                *(unsigned*)&A_lo[wb][g + 8][ncol] = lo;
            }
            __syncthreads();   // wb visible before next layer reads it
        } else {
            // final: y[m] = sum_n W_out[n]*tanh(D+b) + b_out
            const float* bm = b_mid + (size_t)(l * DD + d) * HH + wid * 16;
            const float* wo = W_out + d * HH + wid * 16;
            float pm[2] = {0.0f, 0.0f};
            #pragma unroll
            for (int nt = 0; nt < 2; ++nt) {
                const int ne = nt * 8 + tq * 2;
                const float2 bb = *(const float2*)&bm[ne];
                const float2 ww = *(const float2*)&wo[ne];
                pm[0] = fmaf(tanh_fast(acc[nt][0] + bb.x), ww.x, pm[0]);
                pm[0] = fmaf(tanh_fast(acc[nt][1] + bb.y), ww.y, pm[0]);
                pm[1] = fmaf(tanh_fast(acc[nt][2] + bb.x), ww.x, pm[1]);
                pm[1] = fmaf(tanh_fast(acc[nt][3] + bb.y), ww.y, pm[1]);
            }
            #pragma unroll
            for (int h = 0; h < 2; ++h) {
                pm[h] += __shfl_xor_sync(0xffffffffu, pm[h], 1);
                pm[h] += __shfl_xor_sync(0xffffffffu, pm[h], 2);
            }
            if (tq == 0) {
                red[wid][g]     = pm[0];
                red[wid][g + 8] = pm[1];
            }
            __syncthreads();
            if (t < MTILE) {
                float y = __ldg(&b_out[d]);
                #pragma unroll
                for (int w = 0; w < 16; ++w) y += red[w][t];
                const int pidx = blk * MTILE + t;
                if (pidx < T_TAB) g_table[d][pidx] = y;
                else              g_ymm[d][pidx - T_TAB] = y;  // 0: x=-1, 1: x=+1
            }
        }
    }
}

// ---------------------------------------------------------------------------
// Interp: Catmull-Rom through a SMEM-resident table + min-max normalization.
// 512 blocks x 2048 elems (one net each), 8 elems/thread (measured-best shape).
// ---------------------------------------------------------------------------
__global__ __launch_bounds__(256) void interp_kernel(
    const float* __restrict__ x, float* __restrict__ out)
{
    __shared__ float stab[T_TAB];

    const int t  = threadIdx.x;
    const int d  = blockIdx.x >> 5;          // 32 blocks per net
    const int i8 = blockIdx.x * 256 + t;     // unit of 8 elems (2 float4)

    if (t < T_TAB) stab[t] = g_table[d][t];
    const float ymin = g_ymm[d][0];
    const float s    = 2.0f / (g_ymm[d][1] - ymin);
    __syncthreads();

    const float4 xa = reinterpret_cast<const float4*>(x)[2 * i8];
    const float4 xb = reinterpret_cast<const float4*>(x)[2 * i8 + 1];
    const float xin[8] = {xa.x, xa.y, xa.z, xa.w, xb.x, xb.y, xb.z, xb.w};
    float r[8];
    #pragma unroll
    for (int c = 0; c < 8; ++c) {
        float u = (xin[c] - XMN) * INV_DX;
        u = fminf(fmaxf(u, 0.0f), 141.0f);
        int i = (int)floorf(u);
        i = min(max(i, 1), T_TAB - 3);
        const float tt = u - (float)i;
        const float p0 = stab[i - 1];
        const float p1 = stab[i];
        const float p2 = stab[i + 1];
        const float p3 = stab[i + 2];
        const float y = p1 + 0.5f * tt * ((p2 - p0)
                        + tt * ((2.0f * p0 - 5.0f * p1 + 4.0f * p2 - p3)
                        + tt * (3.0f * (p1 - p2) + p3 - p0)));
        r[c] = fmaf(y - ymin, s, -1.0f);
    }
    reinterpret_cast<float4*>(out)[2 * i8]     = make_float4(r[0], r[1], r[2], r[3]);
    reinterpret_cast<float4*>(out)[2 * i8 + 1] = make_float4(r[4], r[5], r[6], r[7]);
}

// ---------------------------------------------------------------------------
extern "C" void kernel_launch(void* const* d_in, const int* in_sizes, int n_in,
                              void* d_out, int out_size)
{
    const float* x     = (const float*)d_in[0];
    const float* W_in  = (const float*)d_in[1];
    const float* b_in  = (const float*)d_in[2];
    const float* W_mid = (const float*)d_in[3];
    const float* b_mid = (const float*)d_in[4];
    const float* W_out = (const float*)d_in[5];
    const float* b_out = (const float*)d_in[6];

    build_kernel<<<NCTA, 512>>>(W_in, b_in, W_mid, b_mid, W_out, b_out);

    const int total8 = DD * NN / 8;
    interp_kernel<<<total8 / 256, 256>>>(x, (float*)d_out);
}

// round 17
// speedup vs baseline: 1.0375x; 1.0375x over previous
#include <cuda_runtime.h>
#include <cuda_bf16.h>
#include <math.h>
#include <stdint.h>

// ---------------- problem constants ----------------
#define DD 16
#define HH 256
#define MM 3
#define NN 65536

// ---------------- table config ----------------
#define T_TAB 142
#define NPTS  144              // 142 grid + x=-1 + x=+1; 9 M-tiles of 16
#define MTILE 16
#define BPN   9                // blocks per net -> 144 CTAs, one wave
#define XMN   (-6.0f)
#define DXI   (12.0f / 141.0f)
#define INV_DX (141.0f / 12.0f)

// A smem pitch (bf16 elems): multiple of 8 (16B rows for ldmatrix),
// 560B rows -> ldmatrix row phases conflict-free.
#define APITCH 280
#define ABUFB  (MTILE * APITCH * 2)    // bytes per A buffer (8960)

// prep SMEM pitch (fp32): gather banks (8tq + g + 8nt) mod 32: conflict-free.
#define PP2 132

// ---------------- device scratch ----------------
__device__ float g_table[DD][T_TAB];
__device__ float g_ymm[DD][2];
// staged weights in mma-fragment order:
// index (((l*DD+d)*16 + ktile)*32 + ntile)*32 + lane -> {b0h, b1h, b0l, b1l}
__device__ __align__(16) uint4 g_B[MM * DD * 16 * 32 * 32];
#define LSTRIDE (DD * 16 * 32 * 32)    // uint4 elems between layers (262144)

// ==================== helpers ====================
__device__ __forceinline__ uint32_t smem_to_u32(const void* smem_ptr) {
    uint32_t addr;
    asm("{ .reg .u64 tmp; cvta.to.shared.u64 tmp, %1; cvt.u32.u64 %0, tmp; }"
        : "=r"(addr) : "l"(smem_ptr));
    return addr;
}

// exact tanh identity via fast MUFU ex2/rcp: ~1e-7 abs err, saturates correctly
__device__ __forceinline__ float tanh_fast(float x) {
    float e = __expf(2.0f * x);
    return 1.0f - __fdividef(2.0f, e + 1.0f);
}

// (a,b) fp32 -> packed bf16x2 hi + bf16x2 lo (residual); lo16 = a, hi16 = b
__device__ __forceinline__ void split2(float a, float b, unsigned& hi, unsigned& lo) {
    __nv_bfloat16 ha = __float2bfloat16(a), hb = __float2bfloat16(b);
    __nv_bfloat16 la = __float2bfloat16(a - __bfloat162float(ha));
    __nv_bfloat16 lb = __float2bfloat16(b - __bfloat162float(hb));
    hi = (unsigned)__bfloat16_as_ushort(ha) | ((unsigned)__bfloat16_as_ushort(hb) << 16);
    lo = (unsigned)__bfloat16_as_ushort(la) | ((unsigned)__bfloat16_as_ushort(lb) << 16);
}

#define MMA_BF16(d, a, b0, b1) \
    asm volatile("mma.sync.aligned.m16n8k16.row.col.f32.bf16.bf16.f32 " \
        "{%0,%1,%2,%3}, {%4,%5,%6,%7}, {%8,%9}, {%0,%1,%2,%3};" \
        : "+f"((d)[0]), "+f"((d)[1]), "+f"((d)[2]), "+f"((d)[3]) \
        : "r"((a)[0]), "r"((a)[1]), "r"((a)[2]), "r"((a)[3]), "r"(b0), "r"(b1))

#define LDMATRIX_X4(r, addr) \
    asm volatile("ldmatrix.sync.aligned.m8n8.x4.shared.b16 {%0,%1,%2,%3}, [%4];" \
        : "=r"((r)[0]), "=r"((r)[1]), "=r"((r)[2]), "=r"((r)[3]) : "r"(addr))

// ---------------------------------------------------------------------------
// Prep: W_mid fp32 [l][d][k][n] -> g_B fragment-order bf16 hi/lo.
// Block = (nd, ktile, n-half): 1536 blocks x 128 threads. (Verbatim R15;
// merging into build measured slower both times — keep staged + small blocks.)
// ---------------------------------------------------------------------------
__global__ __launch_bounds__(128) void prep_kernel(const float* __restrict__ W_mid)
{
    __shared__ __align__(16) float s[16][PP2];
    const int bid = blockIdx.x;
    const int nh  = bid & 1;            // n half (128 cols)
    const int kt  = (bid >> 1) & 15;    // ktile
    const int nd  = bid >> 5;           // l*16 + d
    const int t   = threadIdx.x;

    // 16 rows x 128 floats, 4 x LDG.128 per thread
    {
        const int r = t >> 3;
        const int c = (t & 7) * 16;
        const float4* src = (const float4*)(W_mid + (size_t)nd * HH * HH
                                + (kt * 16 + r) * HH + nh * 128 + c);
        float4 v0 = __ldg(&src[0]); float4 v1 = __ldg(&src[1]);
        float4 v2 = __ldg(&src[2]); float4 v3 = __ldg(&src[3]);
        *(float4*)&s[r][c]      = v0; *(float4*)&s[r][c + 4]  = v1;
        *(float4*)&s[r][c + 8]  = v2; *(float4*)&s[r][c + 12] = v3;
    }
    __syncthreads();

    const int lane = t & 31;
    const int wid  = t >> 5;
    const int tq   = lane & 3;
    const int g    = lane >> 2;
    const int k0   = 2 * tq;
    uint4* out = g_B + ((size_t)nd * 16 + kt) * 32 * 32;
    #pragma unroll
    for (int it = 0; it < 4; ++it) {
        const int ntl = it * 4 + wid;       // local n-group within half
        const int n   = ntl * 8 + g;
        unsigned b0h, b0l, b1h, b1l;
        split2(s[k0][n],     s[k0 + 1][n], b0h, b0l);
        split2(s[k0 + 8][n], s[k0 + 9][n], b1h, b1l);
        out[(nh * 16 + ntl) * 32 + lane] = make_uint4(b0h, b1h, b0l, b1l);
    }
}

// ---------------------------------------------------------------------------
// Build: per (net, point-tile of 16) CTA, 512 threads (16 warps). Warp w owns
// output columns [16w, 16w+16). 3-term split: AhBh + AlBh + AhBl.
// Double-buffered A (one sync/layer) + cross-layer B prefetch. (Verbatim R15.)
// ---------------------------------------------------------------------------
__global__ __launch_bounds__(512) void build_kernel(
    const float* __restrict__ W_in,  const float* __restrict__ b_in,
    const float* __restrict__ b_mid,
    const float* __restrict__ W_out, const float* __restrict__ b_out)
{
    __shared__ __align__(16) unsigned short A_hi[2][MTILE][APITCH];
    __shared__ __align__(16) unsigned short A_lo[2][MTILE][APITCH];
    __shared__ float red[16][MTILE];

    const int t    = threadIdx.x;
    const int wid  = t >> 5;
    const int lane = t & 31;
    const int tq   = lane & 3;
    const int g    = lane >> 2;
    const int d    = blockIdx.x / BPN;
    const int blk  = blockIdx.x % BPN;

    // hoist layer-0 B fragment load above the input layer (hide latency)
    const uint4* __restrict__ Bw0 =
        g_B + ((size_t)d * 16 * 32 + wid * 2) * 32 + lane;
    uint4 Bc[2];
    Bc[0] = Bw0[0];
    Bc[1] = Bw0[32];

    // ---- input layer: A0[m][k] = tanh(W_in[k]*x_m + b_in[k]) -> buffer 0 ----
    {
        const int m  = t & 15;
        const int kc = t >> 4;        // k chunk of 8
        const int pidx = blk * MTILE + m;
        float xp;
        if (pidx < T_TAB)       xp = XMN + (float)pidx * DXI;
        else if (pidx == T_TAB) xp = -1.0f;
        else                    xp =  1.0f;
        const float* wi = W_in + d * HH;
        const float* bi = b_in + d * HH;
        #pragma unroll
        for (int kk = 0; kk < 8; kk += 2) {
            const int k = kc * 8 + kk;
            const float v0 = tanh_fast(fmaf(__ldg(&wi[k]),     xp, __ldg(&bi[k])));
            const float v1 = tanh_fast(fmaf(__ldg(&wi[k + 1]), xp, __ldg(&bi[k + 1])));
            unsigned hi, lo;
            split2(v0, v1, hi, lo);
            *(unsigned*)&A_hi[0][m][k] = hi;
            *(unsigned*)&A_lo[0][m][k] = lo;
        }
    }
    __syncthreads();

    const uint32_t Ahi_base = smem_to_u32(&A_hi[0][0][0]);
    const uint32_t Alo_base = smem_to_u32(&A_lo[0][0][0]);
    const uint32_t lm_off = (uint32_t)((lane & 15) * (APITCH * 2) + (lane >> 4) * 16);

    for (int l = 0; l < MM; ++l) {
        const int rb = l & 1;
        const int wb = rb ^ 1;
        const uint4* __restrict__ Bw =
            g_B + ((size_t)(l * DD + d) * 16 * 32 + wid * 2) * 32 + lane;
        const uint32_t rboff = (uint32_t)(rb * ABUFB);

        float acc[2][4];
        #pragma unroll
        for (int nt = 0; nt < 2; ++nt)
            #pragma unroll
            for (int e = 0; e < 4; ++e) acc[nt][e] = 0.0f;

        #pragma unroll 4
        for (int kt = 0; kt < 16; ++kt) {
            unsigned ah[4], al[4];
            const uint32_t ka = (uint32_t)(kt * 32);
            LDMATRIX_X4(ah, Ahi_base + rboff + lm_off + ka);
            LDMATRIX_X4(al, Alo_base + rboff + lm_off + ka);

            // prefetch: next k-tile, or next layer's first fragments
            uint4 Bn[2];
            if (kt < 15) {
                #pragma unroll
                for (int nt = 0; nt < 2; ++nt) Bn[nt] = Bw[(kt + 1) * 1024 + nt * 32];
            } else if (l < MM - 1) {
                #pragma unroll
                for (int nt = 0; nt < 2; ++nt) Bn[nt] = Bw[LSTRIDE + nt * 32];
            } else {
                #pragma unroll
                for (int nt = 0; nt < 2; ++nt) Bn[nt] = Bc[nt];
            }

            #pragma unroll
            for (int nt = 0; nt < 2; ++nt) {
                const unsigned b0h = Bc[nt].x, b1h = Bc[nt].y;
                const unsigned b0l = Bc[nt].z, b1l = Bc[nt].w;
                MMA_BF16(acc[nt], ah, b0h, b1h);   // Ahi * Bhi
                MMA_BF16(acc[nt], al, b0h, b1h);   // Alo * Bhi
                MMA_BF16(acc[nt], ah, b0l, b1l);   // Ahi * Blo
            }
            #pragma unroll
            for (int nt = 0; nt < 2; ++nt) Bc[nt] = Bn[nt];
        }

        if (l < MM - 1) {
            // epilogue -> write buffer wb (readers of rb are unaffected)
            const float* bm = b_mid + (size_t)(l * DD + d) * HH + wid * 16;
            #pragma unroll
            for (int nt = 0; nt < 2; ++nt) {
                const int ne = nt * 8 + tq * 2;
                const float2 bb = *(const float2*)&bm[ne];
                const int ncol = wid * 16 + ne;
                unsigned hi, lo;
                split2(tanh_fast(acc[nt][0] + bb.x),
                       tanh_fast(acc[nt][1] + bb.y), hi, lo);
                *(unsigned*)&A_hi[wb][g][ncol] = hi;
                *(unsigned*)&A_lo[wb][g][ncol] = lo;
                split2(tanh_fast(acc[nt][2] + bb.x),
                       tanh_fast(acc[nt][3] + bb.y), hi, lo);
                *(unsigned*)&A_hi[wb][g + 8][ncol] = hi;
                *(unsigned*)&A_lo[wb][g + 8][ncol] = lo;
            }
            __syncthreads();   // wb visible before next layer reads it
        } else {
            // final: y[m] = sum_n W_out[n]*tanh(D+b) + b_out
            const float* bm = b_mid + (size_t)(l * DD + d) * HH + wid * 16;
            const float* wo = W_out + d * HH + wid * 16;
            float pm[2] = {0.0f, 0.0f};
            #pragma unroll
            for (int nt = 0; nt < 2; ++nt) {
                const int ne = nt * 8 + tq * 2;
                const float2 bb = *(const float2*)&bm[ne];
                const float2 ww = *(const float2*)&wo[ne];
                pm[0] = fmaf(tanh_fast(acc[nt][0] + bb.x), ww.x, pm[0]);
                pm[0] = fmaf(tanh_fast(acc[nt][1] + bb.y), ww.y, pm[0]);
                pm[1] = fmaf(tanh_fast(acc[nt][2] + bb.x), ww.x, pm[1]);
                pm[1] = fmaf(tanh_fast(acc[nt][3] + bb.y), ww.y, pm[1]);
            }
            #pragma unroll
            for (int h = 0; h < 2; ++h) {
                pm[h] += __shfl_xor_sync(0xffffffffu, pm[h], 1);
                pm[h] += __shfl_xor_sync(0xffffffffu, pm[h], 2);
            }
            if (tq == 0) {
                red[wid][g]     = pm[0];
                red[wid][g + 8] = pm[1];
            }
            __syncthreads();
            if (t < MTILE) {
                float y = __ldg(&b_out[d]);
                #pragma unroll
                for (int w = 0; w < 16; ++w) y += red[w][t];
                const int pidx = blk * MTILE + t;
                if (pidx < T_TAB) g_table[d][pidx] = y;
                else              g_ymm[d][pidx - T_TAB] = y;  // 0: x=-1, 1: x=+1
            }
        }
    }
}

// ---------------------------------------------------------------------------
// Interp: per-interval cubic COEFFICIENTS (normalization folded in), built
// once per block; per element = 1 LDS.128 + 3 FMA Horner (was 4 scattered
// LDS + ~12 FMA). 512 blocks x 2048 elems (one net each), 8 elems/thread.
// ---------------------------------------------------------------------------
__global__ __launch_bounds__(256) void interp_kernel(
    const float* __restrict__ x, float* __restrict__ out)
{
    __shared__ float tab[T_TAB];
    __shared__ __align__(16) float4 coef[T_TAB];

    const int t  = threadIdx.x;
    const int d  = blockIdx.x >> 5;          // 32 blocks per net
    const int i8 = blockIdx.x * 256 + t;     // unit of 8 elems (2 float4)

    if (t < T_TAB) tab[t] = g_table[d][t];
    const float ymin = g_ymm[d][0];
    const float s    = 2.0f / (g_ymm[d][1] - ymin);
    const float off  = fmaf(-ymin, s, -1.0f);
    __syncthreads();

    // per-interval Catmull-Rom coefs with normalization folded in
    if (t >= 1 && t <= T_TAB - 3) {
        const float p0 = tab[t - 1], p1 = tab[t], p2 = tab[t + 1], p3 = tab[t + 2];
        float4 c;
        c.x = fmaf(p1, s, off);                                        // c0
        c.y = 0.5f * (p2 - p0) * s;                                    // c1
        c.z = 0.5f * (2.0f * p0 - 5.0f * p1 + 4.0f * p2 - p3) * s;     // c2
        c.w = 0.5f * (3.0f * (p1 - p2) + p3 - p0) * s;                 // c3
        coef[t] = c;
    }
    __syncthreads();

    const float4 xa = reinterpret_cast<const float4*>(x)[2 * i8];
    const float4 xb = reinterpret_cast<const float4*>(x)[2 * i8 + 1];
    const float xin[8] = {xa.x, xa.y, xa.z, xa.w, xb.x, xb.y, xb.z, xb.w};
    float r[8];
    #pragma unroll
    for (int c = 0; c < 8; ++c) {
        float u = (xin[c] - XMN) * INV_DX;
        u = fminf(fmaxf(u, 0.0f), 141.0f);
        int i = (int)floorf(u);
        i = min(max(i, 1), T_TAB - 3);
        const float tt = u - (float)i;
        const float4 cf = coef[i];
        r[c] = fmaf(fmaf(fmaf(cf.w, tt, cf.z), tt, cf.y), tt, cf.x);
    }
    reinterpret_cast<float4*>(out)[2 * i8]     = make_float4(r[0], r[1], r[2], r[3]);
    reinterpret_cast<float4*>(out)[2 * i8 + 1] = make_float4(r[4], r[5], r[6], r[7]);
}

// ---------------------------------------------------------------------------
extern "C" void kernel_launch(void* const* d_in, const int* in_sizes, int n_in,
                              void* d_out, int out_size)
{
    const float* x     = (const float*)d_in[0];
    const float* W_in  = (const float*)d_in[1];
    const float* b_in  = (const float*)d_in[2];
    const float* W_mid = (const float*)d_in[3];
    const float* b_mid = (const float*)d_in[4];
    const float* W_out = (const float*)d_in[5];
    const float* b_out = (const float*)d_in[6];

    prep_kernel<<<MM * DD * 32, 128>>>(W_mid);
    build_kernel<<<DD * BPN, 512>>>(W_in, b_in, b_mid, W_out, b_out);

    const int total8 = DD * NN / 8;
    interp_kernel<<<total8 / 256, 256>>>(x, (float*)d_out);
}